// round 15
// baseline (speedup 1.0000x reference)
#include <cuda_runtime.h>

// Swin window attention, 4-kernel split:
//  K0: fuse rel-pos bias + shift mask into g_bm[64][4][49][64] (cols 49-63 = -1e30)
//  K1: qkv GEMM + bias, q pre-scaled, output pre-rounded to tf32 -> g_qkv
//  K2: persistent attention: 2048 CTAs x 8 (window,head) items each,
//      cp.async double-buffered item pipeline -> g_ctx
//  K3: proj GEMM (M=200704, N=128, K=128) + bias -> out
// All GEMMs: mma.sync.m16n8k8 tf32, fragments via ldmatrix.

constexpr int NTOK = 49;
constexpr int NHD  = 4;
constexpr float SCALE = 0.17677669529663687f; // 32^-0.5
constexpr long long TOK = 200704ll;           // 4096 * 49

__device__ float g_qkv[TOK * 384];            // qkv activations (tf32-rounded f32)
__device__ float g_ctx[TOK * 128];            // attention context (f32)
__device__ float g_bm[64 * 4 * 49 * 64 + 64]; // fused bias+mask, stride-64 rows

// ---------------- helpers ----------------
__device__ __forceinline__ unsigned f2tf(float x) {
    unsigned r;
    asm("cvt.rna.tf32.f32 %0, %1;" : "=r"(r) : "f"(x));
    return r;
}
__device__ __forceinline__ float4 f2tf4(float4 v) {
    float4 t;
    t.x = __uint_as_float(f2tf(v.x));
    t.y = __uint_as_float(f2tf(v.y));
    t.z = __uint_as_float(f2tf(v.z));
    t.w = __uint_as_float(f2tf(v.w));
    return t;
}
__device__ __forceinline__ void mma8(float c[4],
                                     unsigned a0, unsigned a1, unsigned a2, unsigned a3,
                                     unsigned b0, unsigned b1) {
    asm volatile(
        "mma.sync.aligned.m16n8k8.row.col.f32.tf32.tf32.f32 "
        "{%0,%1,%2,%3},{%4,%5,%6,%7},{%8,%9},{%0,%1,%2,%3};"
        : "+f"(c[0]), "+f"(c[1]), "+f"(c[2]), "+f"(c[3])
        : "r"(a0), "r"(a1), "r"(a2), "r"(a3), "r"(b0), "r"(b1));
}
__device__ __forceinline__ unsigned sptr(const float* p) {
    return (unsigned)__cvta_generic_to_shared(p);
}
__device__ __forceinline__ void ldA(unsigned r[4], const float* base, int L) {
    int lane = threadIdx.x & 31;
    const float* p = base + ((lane & 7) + ((lane & 8) ? 8 : 0)) * L + ((lane & 16) ? 4 : 0);
    unsigned a = sptr(p);
    asm volatile("ldmatrix.sync.aligned.m8n8.x4.shared.b16 {%0,%1,%2,%3}, [%4];"
                 : "=r"(r[0]), "=r"(r[1]), "=r"(r[2]), "=r"(r[3]) : "r"(a));
}
__device__ __forceinline__ void ldB(unsigned r[2], const float* base, int L) {
    int lane = threadIdx.x & 31;
    const float* p = base + (lane & 7) * L + ((lane & 8) ? 4 : 0);
    unsigned a = sptr(p);
    asm volatile("ldmatrix.sync.aligned.m8n8.x2.shared.b16 {%0,%1}, [%2];"
                 : "=r"(r[0]), "=r"(r[1]) : "r"(a));
}
__device__ __forceinline__ unsigned ldsm(const float* p) { return __float_as_uint(*p); }

#define CP_ASYNC16(dst, src) \
    asm volatile("cp.async.cg.shared.global [%0], [%1], 16;" :: "r"(dst), "l"(src))
#define CP_COMMIT() asm volatile("cp.async.commit_group;")
#define CP_WAIT(N)  asm volatile("cp.async.wait_group %0;" :: "n"(N))

// ---------------- K0: fused bias+mask table (padded stride-64 rows) ----------------
__global__ void biasfuse_kernel(const float* __restrict__ tbl,
                                const int*   __restrict__ idx,
                                const float* __restrict__ mask) {
    long i = (long)blockIdx.x * 256 + threadIdx.x;   // 64*4*49*64 = 802816 exactly
    int m = (int)(i & 63);
    long r = i >> 6;
    int n = (int)(r % 49); r /= 49;
    int h = (int)(r & 3);
    int wn = (int)(r >> 2);
    float v = -1e30f;                                // pad cols 49..63 -> exp() = 0
    if (m < NTOK)
        v = __ldg(tbl + __ldg(idx + n * 49 + m) * NHD + h)
          + __ldg(mask + wn * 2401 + n * 49 + m);
    g_bm[i] = v;
}

// ---------------- K1/K3: GEMM  C[M,N] = A[M,128] @ W[N,128]^T + bias ----------------
constexpr int GA = 0;                 // A tile 128 x 132
constexpr int GB = 128 * 132;         // B chunk 64 x 132
constexpr int GEMM_SMEM = (128 * 132 + 64 * 132) * 4;   // 101376 B

__global__ __launch_bounds__(256, 2)
void gemm_tf32_kernel(const float* __restrict__ A,
                      const float* __restrict__ W,
                      const float* __restrict__ bias,
                      float* __restrict__ C,
                      int ldc, int n_chunks, int rnd) {
    extern __shared__ float sm[];
    const int tid = threadIdx.x, lane = tid & 31, w = tid >> 5;
    const int wm = w & 3, wn = w >> 2;
    const int ar = lane >> 2, ac = lane & 3;
    const long mt = blockIdx.x;

    {
        const float4* ag = (const float4*)(A + mt * 128 * 128);
        #pragma unroll
        for (int i = 0; i < 16; ++i) {
            int j = tid + i * 256;
            int r = j >> 5, c4 = j & 31;
            *(float4*)(sm + GA + r * 132 + c4 * 4) = f2tf4(__ldg(ag + j));
        }
    }
    {
        const float4* wg = (const float4*)W;
        #pragma unroll
        for (int i = 0; i < 8; ++i) {
            int j = tid + i * 256;
            int r = j >> 5, c4 = j & 31;
            *(float4*)(sm + GB + r * 132 + c4 * 4) = f2tf4(__ldg(wg + j));
        }
    }
    __syncthreads();

    for (int nt = 0; nt < n_chunks; ++nt) {
        float4 breg[8];
        const bool pf = (nt + 1 < n_chunks);
        if (pf) {
            const float4* wg = (const float4*)(W + (long)(nt + 1) * 64 * 128);
            #pragma unroll
            for (int i = 0; i < 8; ++i) breg[i] = __ldg(wg + tid + i * 256);
        }

        float acc[2][4][4];
        #pragma unroll
        for (int hf = 0; hf < 2; ++hf)
            #pragma unroll
            for (int t = 0; t < 4; ++t)
                #pragma unroll
                for (int j = 0; j < 4; ++j) acc[hf][t][j] = 0.f;

        #pragma unroll 4
        for (int k0 = 0; k0 < 128; k0 += 8) {
            unsigned a0[4], a1[4];
            ldA(a0, sm + GA + (wm * 32) * 132 + k0, 132);
            ldA(a1, sm + GA + (wm * 32 + 16) * 132 + k0, 132);
            #pragma unroll
            for (int t = 0; t < 4; ++t) {
                unsigned bb[2];
                ldB(bb, sm + GB + (wn * 32 + t * 8) * 132 + k0, 132);
                mma8(acc[0][t], a0[0], a0[1], a0[2], a0[3], bb[0], bb[1]);
                mma8(acc[1][t], a1[0], a1[1], a1[2], a1[3], bb[0], bb[1]);
            }
        }

        #pragma unroll
        for (int hf = 0; hf < 2; ++hf)
            #pragma unroll
            for (int t = 0; t < 4; ++t) {
                int col = nt * 64 + wn * 32 + t * 8 + 2 * ac;
                float sc = (rnd && col < 128) ? SCALE : 1.f;
                float b0v = __ldg(bias + col);
                float b1v = __ldg(bias + col + 1);
                long row = mt * 128 + wm * 32 + hf * 16 + ar;
                float o0 = (acc[hf][t][0] + b0v) * sc;
                float o1 = (acc[hf][t][1] + b1v) * sc;
                float o2 = (acc[hf][t][2] + b0v) * sc;
                float o3 = (acc[hf][t][3] + b1v) * sc;
                if (rnd) {
                    o0 = __uint_as_float(f2tf(o0));
                    o1 = __uint_as_float(f2tf(o1));
                    o2 = __uint_as_float(f2tf(o2));
                    o3 = __uint_as_float(f2tf(o3));
                }
                C[row * ldc + col]            = o0;
                C[row * ldc + col + 1]        = o1;
                C[(row + 8) * ldc + col]      = o2;
                C[(row + 8) * ldc + col + 1]  = o3;
            }

        if (pf) {
            __syncthreads();
            #pragma unroll
            for (int i = 0; i < 8; ++i) {
                int j = tid + i * 256;
                int r = j >> 5, c4 = j & 31;
                *(float4*)(sm + GB + r * 132 + c4 * 4) = f2tf4(breg[i]);
            }
            __syncthreads();
        }
    }
}

// ---------------- K2: persistent attention, cp.async item pipeline ----------------
// 2048 CTAs x 128 thr; each CTA runs 8 (window,head) items with double-buffered
// smem (2 x 28672 B = 57344 B -> 4 CTAs/SM). Staging of item i+1 overlaps
// compute of item i. Pad rows zeroed once per buffer (cp.async never writes them).
constexpr int QS3 = 0;                   // Q 64 x 36
constexpr int KS3 = QS3 + 64 * 36;       // K 64 x 36 (pad rows zeroed)
constexpr int VS3 = KS3 + 64 * 36;       // V 64 x 40 (pad rows zeroed)
constexpr int BUF3 = VS3 + 64 * 40;      // 7168 floats per buffer
constexpr int ATTN_SMEM = 2 * BUF3 * 4;  // 57344 B
constexpr int ITEMS_PER_CTA = 8;

__device__ __forceinline__ void stage_item(float* buf, int j) {
    const int tid = threadIdx.x;
    const int win = j >> 2, h = j & 3;
    const float* qb = g_qkv + (long)win * NTOK * 384 + h * 32;
    for (int i = tid; i < NTOK * 8; i += 128) {
        int r = i >> 3, c4 = (i & 7) * 4;
        long off = (long)r * 384 + c4;
        CP_ASYNC16(sptr(buf + QS3 + r * 36 + c4), qb + off);
        CP_ASYNC16(sptr(buf + KS3 + r * 36 + c4), qb + 128 + off);
        CP_ASYNC16(sptr(buf + VS3 + r * 40 + c4), qb + 256 + off);
    }
    CP_COMMIT();
}

__device__ __forceinline__ void compute_item(float* sm, int j) {
    const int tid = threadIdx.x, lane = tid & 31, wm = tid >> 5;
    const int ar = lane >> 2, ac = lane & 3;
    const int win = j >> 2, h = j & 3;
    const long tok0 = (long)win * NTOK;

    // ---- scores S = Q_h @ K_h^T (64x64, K=32); warp tile 16x64 ----
    float sacc[8][4];
    #pragma unroll
    for (int t = 0; t < 8; ++t)
        #pragma unroll
        for (int jj = 0; jj < 4; ++jj) sacc[t][jj] = 0.f;

    #pragma unroll
    for (int kk = 0; kk < 4; ++kk) {
        int k0 = kk * 8;
        unsigned a[4];
        ldA(a, sm + QS3 + (wm * 16) * 36 + k0, 36);
        #pragma unroll
        for (int t = 0; t < 8; ++t) {
            unsigned bb[2];
            ldB(bb, sm + KS3 + (t * 8) * 36 + k0, 36);
            mma8(sacc[t], a[0], a[1], a[2], a[3], bb[0], bb[1]);
        }
    }

    // ---- softmax numerator, predicate-free (bias pad cols = -1e30 -> e = 0) ----
    const int r0 = wm * 16 + ar, r1 = r0 + 8;
    const bool r0ok = r0 < NTOK, r1ok = r1 < NTOK;
    const float* bmh = g_bm + (size_t)(((win & 63) * 4 + h) * 49) * 64;

    float psum0 = 0.f, psum1 = 0.f;
    #pragma unroll
    for (int t = 0; t < 8; ++t) {
        int m0 = t * 8 + 2 * ac;
        float2 bA = r0ok ? __ldg((const float2*)(bmh + r0 * 64 + m0))
                         : make_float2(0.f, 0.f);
        float2 bB = r1ok ? __ldg((const float2*)(bmh + r1 * 64 + m0))
                         : make_float2(0.f, 0.f);
        float e0 = __expf(sacc[t][0] + bA.x);
        float e1 = __expf(sacc[t][1] + bA.y);
        float e2 = __expf(sacc[t][2] + bB.x);
        float e3 = __expf(sacc[t][3] + bB.y);
        psum0 += e0 + e1;
        psum1 += e2 + e3;
        sacc[t][0] = __uint_as_float(f2tf(e0));
        sacc[t][1] = __uint_as_float(f2tf(e1));
        sacc[t][2] = __uint_as_float(f2tf(e2));
        sacc[t][3] = __uint_as_float(f2tf(e3));
    }
    psum0 += __shfl_xor_sync(0xffffffffu, psum0, 1);
    psum0 += __shfl_xor_sync(0xffffffffu, psum0, 2);
    psum1 += __shfl_xor_sync(0xffffffffu, psum1, 1);
    psum1 += __shfl_xor_sync(0xffffffffu, psum1, 2);
    const float inv0 = r0ok ? __fdividef(1.f, psum0) : 0.f;
    const float inv1 = r1ok ? __fdividef(1.f, psum1) : 0.f;

    // ---- ctx = (E @ V_h) * inv: shuffle-transpose C-frag -> A-frag per k-tile ----
    float cacc[4][4];
    #pragma unroll
    for (int u = 0; u < 4; ++u)
        #pragma unroll
        for (int jj = 0; jj < 4; ++jj) cacc[u][jj] = 0.f;

    const int sl0 = (lane & 28) | (ac >> 1);
    const bool odd = ac & 1;
    #pragma unroll
    for (int kk = 0; kk < 8; ++kk) {
        float q0 = __shfl_sync(0xffffffffu, sacc[kk][0], sl0);
        float q1 = __shfl_sync(0xffffffffu, sacc[kk][1], sl0);
        float q2 = __shfl_sync(0xffffffffu, sacc[kk][2], sl0);
        float q3 = __shfl_sync(0xffffffffu, sacc[kk][3], sl0);
        float s0 = __shfl_sync(0xffffffffu, sacc[kk][0], sl0 + 2);
        float s1 = __shfl_sync(0xffffffffu, sacc[kk][1], sl0 + 2);
        float s2 = __shfl_sync(0xffffffffu, sacc[kk][2], sl0 + 2);
        float s3 = __shfl_sync(0xffffffffu, sacc[kk][3], sl0 + 2);
        unsigned a0 = __float_as_uint(odd ? q1 : q0);
        unsigned a1 = __float_as_uint(odd ? q3 : q2);
        unsigned a2 = __float_as_uint(odd ? s1 : s0);
        unsigned a3 = __float_as_uint(odd ? s3 : s2);
        #pragma unroll
        for (int u = 0; u < 4; ++u) {
            unsigned b0 = ldsm(sm + VS3 + (kk * 8 + ac) * 40 + u * 8 + ar);
            unsigned b1 = ldsm(sm + VS3 + (kk * 8 + 4 + ac) * 40 + u * 8 + ar);
            mma8(cacc[u], a0, a1, a2, a3, b0, b1);
        }
    }
    #pragma unroll
    for (int u = 0; u < 4; ++u) {
        int col = h * 32 + u * 8 + 2 * ac;
        if (r0ok)
            *(float2*)(g_ctx + (tok0 + r0) * 128 + col) =
                make_float2(cacc[u][0] * inv0, cacc[u][1] * inv0);
        if (r1ok)
            *(float2*)(g_ctx + (tok0 + r1) * 128 + col) =
                make_float2(cacc[u][2] * inv1, cacc[u][3] * inv1);
    }
}

__global__ __launch_bounds__(128, 4)
void attn_kernel() {
    extern __shared__ float sm[];
    const int tid = threadIdx.x;
    const int base = blockIdx.x * ITEMS_PER_CTA;

    // zero K and V pad rows (49..63) in BOTH buffers, once
    {
        const float4 z = make_float4(0.f, 0.f, 0.f, 0.f);
        for (int i = tid; i < 2 * 15 * 16; i += 128) {
            int bi = i / (15 * 16);
            int j = i - bi * (15 * 16);
            int isv = (j >= 120);
            int jj = isv ? j - 120 : j;
            int r = 49 + (jj >> 3), c4 = (jj & 7) * 4;
            float* dst = sm + bi * BUF3 + (isv ? VS3 + r * 40 + c4 : KS3 + r * 36 + c4);
            *(float4*)dst = z;
        }
    }
    // prologue: stage item 0 into buffer 0
    stage_item(sm, base);

    #pragma unroll 1
    for (int it = 0; it < ITEMS_PER_CTA; ++it) {
        if (it + 1 < ITEMS_PER_CTA) {
            stage_item(sm + ((it + 1) & 1) * BUF3, base + it + 1);
            CP_WAIT(1);          // item it's group complete
        } else {
            CP_WAIT(0);
        }
        __syncthreads();         // staged data visible to all warps
        compute_item(sm + (it & 1) * BUF3, base + it);
        __syncthreads();         // all warps done reading before buffer reuse
    }
}

// ---------------- launch ----------------
extern "C" void kernel_launch(void* const* d_in, const int* in_sizes, int n_in,
                              void* d_out, int out_size) {
    const float* x      = (const float*)d_in[0];
    const float* mask   = (const float*)d_in[1];
    const float* qkv_w  = (const float*)d_in[2];
    const float* qkv_b  = (const float*)d_in[3];
    const float* proj_w = (const float*)d_in[4];
    const float* proj_b = (const float*)d_in[5];
    const float* tbl    = (const float*)d_in[6];
    const int*   idx    = (const int*)d_in[7];

    cudaFuncSetAttribute(gemm_tf32_kernel,
                         cudaFuncAttributeMaxDynamicSharedMemorySize, GEMM_SMEM);
    cudaFuncSetAttribute(attn_kernel,
                         cudaFuncAttributeMaxDynamicSharedMemorySize, ATTN_SMEM);

    float* qkv_s; cudaGetSymbolAddress((void**)&qkv_s, g_qkv);
    float* ctx_s; cudaGetSymbolAddress((void**)&ctx_s, g_ctx);

    // K0: fused bias+mask (padded layout): 802816 / 256 = 3136 blocks
    biasfuse_kernel<<<3136, 256>>>(tbl, idx, mask);

    // K1: qkv GEMM (M=200704, N=384), output tf32-pre-rounded
    gemm_tf32_kernel<<<1568, 256, GEMM_SMEM>>>(x, qkv_w, qkv_b, qkv_s, 384, 6, 1);

    // K2: persistent attention, 2048 CTAs x 8 items
    attn_kernel<<<2048, 128, ATTN_SMEM>>>();

    // K3: proj GEMM (M=200704, N=128), plain f32 output
    gemm_tf32_kernel<<<1568, 256, GEMM_SMEM>>>(ctx_s, proj_w, proj_b,
                                               (float*)d_out, 128, 2, 0);
}

// round 17
// speedup vs baseline: 1.0553x; 1.0553x over previous
#include <cuda_runtime.h>

// Swin window attention, 4-kernel split:
//  K0: fuse rel-pos bias + shift mask into g_bm[64][4][64][64] (pads = -1e30)
//  K1: qkv GEMM + bias, q pre-scaled, output pre-rounded to tf32 -> g_qkv
//  K2: per-(window, head) attention -> g_ctx; score accumulators INITIALIZED
//      with bias (loads issue before the MMA chain, latency hidden)
//  K3: proj GEMM (M=200704, N=128, K=128) + bias -> out
// All GEMMs: mma.sync.m16n8k8 tf32, fragments via ldmatrix.

constexpr int NTOK = 49;
constexpr int NHD  = 4;
constexpr float SCALE = 0.17677669529663687f; // 32^-0.5
constexpr long long TOK = 200704ll;           // 4096 * 49

__device__ float g_qkv[TOK * 384];              // qkv activations (tf32-rounded f32)
__device__ float g_ctx[TOK * 128];              // attention context (f32)
// +1024 slack: the unpredicated bias seed reads up to 8 rows (512 floats) past
// the last tile (rows with r1>=64 are discarded by the r1ok guard downstream).
__device__ float g_bm[64 * 4 * 64 * 64 + 1024];

// ---------------- helpers ----------------
__device__ __forceinline__ unsigned f2tf(float x) {
    unsigned r;
    asm("cvt.rna.tf32.f32 %0, %1;" : "=r"(r) : "f"(x));
    return r;
}
__device__ __forceinline__ float4 f2tf4(float4 v) {
    float4 t;
    t.x = __uint_as_float(f2tf(v.x));
    t.y = __uint_as_float(f2tf(v.y));
    t.z = __uint_as_float(f2tf(v.z));
    t.w = __uint_as_float(f2tf(v.w));
    return t;
}
__device__ __forceinline__ void mma8(float c[4],
                                     unsigned a0, unsigned a1, unsigned a2, unsigned a3,
                                     unsigned b0, unsigned b1) {
    asm volatile(
        "mma.sync.aligned.m16n8k8.row.col.f32.tf32.tf32.f32 "
        "{%0,%1,%2,%3},{%4,%5,%6,%7},{%8,%9},{%0,%1,%2,%3};"
        : "+f"(c[0]), "+f"(c[1]), "+f"(c[2]), "+f"(c[3])
        : "r"(a0), "r"(a1), "r"(a2), "r"(a3), "r"(b0), "r"(b1));
}
__device__ __forceinline__ unsigned sptr(const float* p) {
    return (unsigned)__cvta_generic_to_shared(p);
}
__device__ __forceinline__ void ldA(unsigned r[4], const float* base, int L) {
    int lane = threadIdx.x & 31;
    const float* p = base + ((lane & 7) + ((lane & 8) ? 8 : 0)) * L + ((lane & 16) ? 4 : 0);
    unsigned a = sptr(p);
    asm volatile("ldmatrix.sync.aligned.m8n8.x4.shared.b16 {%0,%1,%2,%3}, [%4];"
                 : "=r"(r[0]), "=r"(r[1]), "=r"(r[2]), "=r"(r[3]) : "r"(a));
}
__device__ __forceinline__ void ldB(unsigned r[2], const float* base, int L) {
    int lane = threadIdx.x & 31;
    const float* p = base + (lane & 7) * L + ((lane & 8) ? 4 : 0);
    unsigned a = sptr(p);
    asm volatile("ldmatrix.sync.aligned.m8n8.x2.shared.b16 {%0,%1}, [%2];"
                 : "=r"(r[0]), "=r"(r[1]) : "r"(a));
}
__device__ __forceinline__ unsigned ldsm(const float* p) { return __float_as_uint(*p); }

// ---------------- K0: fused bias+mask table (64x64 padded tiles) ----------------
__global__ void biasfuse_kernel(const float* __restrict__ tbl,
                                const int*   __restrict__ idx,
                                const float* __restrict__ mask) {
    long i = (long)blockIdx.x * 256 + threadIdx.x;   // 64*4*64*64 = 1048576 exactly
    int m = (int)(i & 63);
    long r = i >> 6;
    int n = (int)(r & 63); r >>= 6;
    int h = (int)(r & 3);
    int wn = (int)(r >> 2);
    float v = -1e30f;                                // pad rows/cols -> exp() = 0
    if (m < NTOK && n < NTOK)
        v = __ldg(tbl + __ldg(idx + n * 49 + m) * NHD + h)
          + __ldg(mask + wn * 2401 + n * 49 + m);
    g_bm[i] = v;
}

// zero the overrun slack once so OOB-row seeds are finite (0 -> e=1, discarded)
__global__ void bmslack_kernel() {
    g_bm[64 * 4 * 64 * 64 + blockIdx.x * 256 + threadIdx.x] = 0.f;
}

// ---------------- K1/K3: GEMM  C[M,N] = A[M,128] @ W[N,128]^T + bias ----------------
constexpr int GA = 0;                 // A tile 128 x 132
constexpr int GB = 128 * 132;         // B chunk 64 x 132
constexpr int GEMM_SMEM = (128 * 132 + 64 * 132) * 4;   // 101376 B

__global__ __launch_bounds__(256, 2)
void gemm_tf32_kernel(const float* __restrict__ A,
                      const float* __restrict__ W,
                      const float* __restrict__ bias,
                      float* __restrict__ C,
                      int ldc, int n_chunks, int rnd) {
    extern __shared__ float sm[];
    const int tid = threadIdx.x, lane = tid & 31, w = tid >> 5;
    const int wm = w & 3, wn = w >> 2;
    const int ar = lane >> 2, ac = lane & 3;
    const long mt = blockIdx.x;

    {
        const float4* ag = (const float4*)(A + mt * 128 * 128);
        #pragma unroll
        for (int i = 0; i < 16; ++i) {
            int j = tid + i * 256;
            int r = j >> 5, c4 = j & 31;
            *(float4*)(sm + GA + r * 132 + c4 * 4) = f2tf4(__ldg(ag + j));
        }
    }
    {
        const float4* wg = (const float4*)W;
        #pragma unroll
        for (int i = 0; i < 8; ++i) {
            int j = tid + i * 256;
            int r = j >> 5, c4 = j & 31;
            *(float4*)(sm + GB + r * 132 + c4 * 4) = f2tf4(__ldg(wg + j));
        }
    }
    __syncthreads();

    for (int nt = 0; nt < n_chunks; ++nt) {
        float4 breg[8];
        const bool pf = (nt + 1 < n_chunks);
        if (pf) {
            const float4* wg = (const float4*)(W + (long)(nt + 1) * 64 * 128);
            #pragma unroll
            for (int i = 0; i < 8; ++i) breg[i] = __ldg(wg + tid + i * 256);
        }

        float acc[2][4][4];
        #pragma unroll
        for (int hf = 0; hf < 2; ++hf)
            #pragma unroll
            for (int t = 0; t < 4; ++t)
                #pragma unroll
                for (int j = 0; j < 4; ++j) acc[hf][t][j] = 0.f;

        #pragma unroll 4
        for (int k0 = 0; k0 < 128; k0 += 8) {
            unsigned a0[4], a1[4];
            ldA(a0, sm + GA + (wm * 32) * 132 + k0, 132);
            ldA(a1, sm + GA + (wm * 32 + 16) * 132 + k0, 132);
            #pragma unroll
            for (int t = 0; t < 4; ++t) {
                unsigned bb[2];
                ldB(bb, sm + GB + (wn * 32 + t * 8) * 132 + k0, 132);
                mma8(acc[0][t], a0[0], a0[1], a0[2], a0[3], bb[0], bb[1]);
                mma8(acc[1][t], a1[0], a1[1], a1[2], a1[3], bb[0], bb[1]);
            }
        }

        #pragma unroll
        for (int hf = 0; hf < 2; ++hf)
            #pragma unroll
            for (int t = 0; t < 4; ++t) {
                int col = nt * 64 + wn * 32 + t * 8 + 2 * ac;
                float sc = (rnd && col < 128) ? SCALE : 1.f;
                float b0v = __ldg(bias + col);
                float b1v = __ldg(bias + col + 1);
                long row = mt * 128 + wm * 32 + hf * 16 + ar;
                float o0 = (acc[hf][t][0] + b0v) * sc;
                float o1 = (acc[hf][t][1] + b1v) * sc;
                float o2 = (acc[hf][t][2] + b0v) * sc;
                float o3 = (acc[hf][t][3] + b1v) * sc;
                if (rnd) {
                    o0 = __uint_as_float(f2tf(o0));
                    o1 = __uint_as_float(f2tf(o1));
                    o2 = __uint_as_float(f2tf(o2));
                    o3 = __uint_as_float(f2tf(o3));
                }
                C[row * ldc + col]            = o0;
                C[row * ldc + col + 1]        = o1;
                C[(row + 8) * ldc + col]      = o2;
                C[(row + 8) * ldc + col + 1]  = o3;
            }

        if (pf) {
            __syncthreads();
            #pragma unroll
            for (int i = 0; i < 8; ++i) {
                int j = tid + i * 256;
                int r = j >> 5, c4 = j & 31;
                *(float4*)(sm + GB + r * 132 + c4 * 4) = f2tf4(breg[i]);
            }
            __syncthreads();
        }
    }
}

// ---------------- K2: attention per (window, head) ----------------
// 128 thr / 4 warps; warp wm owns rows [16*wm, 16*wm+16).
// Score accumulators seeded with bias+mask (unpredicated loads issued before
// the QK MMA chain -> L2 latency hidden under ~32 MMAs). Rows >= 64 read the
// zeroed slack region; their results land only in guarded c[2]/c[3] outputs.
constexpr int QS3 = 0;                   // Q 64 x 36
constexpr int KS3 = QS3 + 64 * 36;       // K 64 x 36 (pad rows zeroed)
constexpr int VS3 = KS3 + 64 * 36;       // V 64 x 40 (pad rows zeroed)
constexpr int ATTN_SMEM = (VS3 + 64 * 40) * 4;   // 28672 B -> 7 CTAs/SM

__global__ __launch_bounds__(128, 7)
void attn_kernel() {
    extern __shared__ float sm[];
    const int tid = threadIdx.x, lane = tid & 31, wm = tid >> 5;
    const int ar = lane >> 2, ac = lane & 3;
    const int win = blockIdx.x, h = blockIdx.y;
    const long tok0 = (long)win * NTOK;

    // zero K and V pad rows (49..63): pad-col scores stay finite (bias -1e30
    // dominates); V pads so 0*garbage can't poison PV.
    {
        const float4 z = make_float4(0.f, 0.f, 0.f, 0.f);
        for (int i = tid; i < 15 * 16; i += 128) {
            int b = (i >= 120);
            int j = b ? i - 120 : i;
            int r = 49 + (j >> 3), c4 = (j & 7) * 4;
            float* dst = b ? (sm + VS3 + r * 40 + c4) : (sm + KS3 + r * 36 + c4);
            *(float4*)dst = z;
        }
    }
    // stage q,k,v (49 rows x 32 cols each) — already tf32-rounded by K1
    {
        const float* qb = g_qkv + tok0 * 384 + h * 32;
        const float* kb = qb + 128;
        const float* vb = qb + 256;
        for (int i = tid; i < NTOK * 8; i += 128) {
            int r = i >> 3, c4 = (i & 7) * 4;
            long off = (long)r * 384 + c4;
            *(float4*)(sm + QS3 + r * 36 + c4) = __ldg((const float4*)(qb + off));
            *(float4*)(sm + KS3 + r * 36 + c4) = __ldg((const float4*)(kb + off));
            *(float4*)(sm + VS3 + r * 40 + c4) = __ldg((const float4*)(vb + off));
        }
    }

    // ---- seed score accumulators with bias+mask (C-fragment layout) ----
    const int r0 = wm * 16 + ar, r1 = r0 + 8;
    const bool r0ok = r0 < NTOK, r1ok = r1 < NTOK;
    const float* bmh = g_bm + (size_t)((win & 63) * 4 + h) * 4096;

    float sacc[8][4];
    #pragma unroll
    for (int t = 0; t < 8; ++t) {
        int m0 = t * 8 + 2 * ac;
        float2 bA = __ldg((const float2*)(bmh + r0 * 64 + m0));
        float2 bB = __ldg((const float2*)(bmh + r1 * 64 + m0));   // r1<=71: slack-safe
        sacc[t][0] = bA.x; sacc[t][1] = bA.y;
        sacc[t][2] = bB.x; sacc[t][3] = bB.y;
    }
    __syncthreads();

    // ---- scores S = bias + Q_h @ K_h^T (64x64, K=32); warp tile 16x64 ----
    #pragma unroll
    for (int kk = 0; kk < 4; ++kk) {
        int k0 = kk * 8;
        unsigned a[4];
        ldA(a, sm + QS3 + (wm * 16) * 36 + k0, 36);
        #pragma unroll
        for (int t = 0; t < 8; ++t) {
            unsigned bb[2];
            ldB(bb, sm + KS3 + (t * 8) * 36 + k0, 36);
            mma8(sacc[t], a[0], a[1], a[2], a[3], bb[0], bb[1]);
        }
    }

    // ---- softmax numerator: pure exp (pad cols/rows carry -1e30 -> e = 0) ----
    float psum0 = 0.f, psum1 = 0.f;
    #pragma unroll
    for (int t = 0; t < 8; ++t) {
        float e0 = __expf(sacc[t][0]);
        float e1 = __expf(sacc[t][1]);
        float e2 = __expf(sacc[t][2]);
        float e3 = __expf(sacc[t][3]);
        psum0 += e0 + e1;
        psum1 += e2 + e3;
        sacc[t][0] = __uint_as_float(f2tf(e0));
        sacc[t][1] = __uint_as_float(f2tf(e1));
        sacc[t][2] = __uint_as_float(f2tf(e2));
        sacc[t][3] = __uint_as_float(f2tf(e3));
    }
    psum0 += __shfl_xor_sync(0xffffffffu, psum0, 1);
    psum0 += __shfl_xor_sync(0xffffffffu, psum0, 2);
    psum1 += __shfl_xor_sync(0xffffffffu, psum1, 1);
    psum1 += __shfl_xor_sync(0xffffffffu, psum1, 2);
    const float inv0 = r0ok ? __fdividef(1.f, psum0) : 0.f;
    const float inv1 = r1ok ? __fdividef(1.f, psum1) : 0.f;

    // ---- ctx = (E @ V_h) * inv: shuffle-transpose C-frag -> A-frag per k-tile ----
    float cacc[4][4];
    #pragma unroll
    for (int u = 0; u < 4; ++u)
        #pragma unroll
        for (int jj = 0; jj < 4; ++jj) cacc[u][jj] = 0.f;

    const int sl0 = (lane & 28) | (ac >> 1);
    const bool odd = ac & 1;
    #pragma unroll
    for (int kk = 0; kk < 8; ++kk) {
        float q0 = __shfl_sync(0xffffffffu, sacc[kk][0], sl0);
        float q1 = __shfl_sync(0xffffffffu, sacc[kk][1], sl0);
        float q2 = __shfl_sync(0xffffffffu, sacc[kk][2], sl0);
        float q3 = __shfl_sync(0xffffffffu, sacc[kk][3], sl0);
        float s0 = __shfl_sync(0xffffffffu, sacc[kk][0], sl0 + 2);
        float s1 = __shfl_sync(0xffffffffu, sacc[kk][1], sl0 + 2);
        float s2 = __shfl_sync(0xffffffffu, sacc[kk][2], sl0 + 2);
        float s3 = __shfl_sync(0xffffffffu, sacc[kk][3], sl0 + 2);
        unsigned a0 = __float_as_uint(odd ? q1 : q0);
        unsigned a1 = __float_as_uint(odd ? q3 : q2);
        unsigned a2 = __float_as_uint(odd ? s1 : s0);
        unsigned a3 = __float_as_uint(odd ? s3 : s2);
        #pragma unroll
        for (int u = 0; u < 4; ++u) {
            unsigned b0 = ldsm(sm + VS3 + (kk * 8 + ac) * 40 + u * 8 + ar);
            unsigned b1 = ldsm(sm + VS3 + (kk * 8 + 4 + ac) * 40 + u * 8 + ar);
            mma8(cacc[u], a0, a1, a2, a3, b0, b1);
        }
    }
    #pragma unroll
    for (int u = 0; u < 4; ++u) {
        int col = h * 32 + u * 8 + 2 * ac;
        if (r0ok)
            *(float2*)(g_ctx + (tok0 + r0) * 128 + col) =
                make_float2(cacc[u][0] * inv0, cacc[u][1] * inv0);
        if (r1ok)
            *(float2*)(g_ctx + (tok0 + r1) * 128 + col) =
                make_float2(cacc[u][2] * inv1, cacc[u][3] * inv1);
    }
}

// ---------------- launch ----------------
extern "C" void kernel_launch(void* const* d_in, const int* in_sizes, int n_in,
                              void* d_out, int out_size) {
    const float* x      = (const float*)d_in[0];
    const float* mask   = (const float*)d_in[1];
    const float* qkv_w  = (const float*)d_in[2];
    const float* qkv_b  = (const float*)d_in[3];
    const float* proj_w = (const float*)d_in[4];
    const float* proj_b = (const float*)d_in[5];
    const float* tbl    = (const float*)d_in[6];
    const int*   idx    = (const int*)d_in[7];

    cudaFuncSetAttribute(gemm_tf32_kernel,
                         cudaFuncAttributeMaxDynamicSharedMemorySize, GEMM_SMEM);
    cudaFuncSetAttribute(attn_kernel,
                         cudaFuncAttributeMaxDynamicSharedMemorySize, ATTN_SMEM);

    float* qkv_s; cudaGetSymbolAddress((void**)&qkv_s, g_qkv);
    float* ctx_s; cudaGetSymbolAddress((void**)&ctx_s, g_ctx);

    // K0: fused bias+mask (64x64 padded): 1048576 / 256 = 4096 blocks
    biasfuse_kernel<<<4096, 256>>>(tbl, idx, mask);
    bmslack_kernel<<<4, 256>>>();   // zero the 1024-float overrun slack

    // K1: qkv GEMM (M=200704, N=384), output tf32-pre-rounded
    gemm_tf32_kernel<<<1568, 256, GEMM_SMEM>>>(x, qkv_w, qkv_b, qkv_s, 384, 6, 1);

    // K2: attention, one (window, head) per CTA
    {
        dim3 grid(4096, 4);
        attn_kernel<<<grid, 128, ATTN_SMEM>>>();
    }

    // K3: proj GEMM (M=200704, N=128), plain f32 output
    gemm_tf32_kernel<<<1568, 256, GEMM_SMEM>>>(ctx_s, proj_w, proj_b,
                                               (float*)d_out, 128, 2, 0);
}